// round 13
// baseline (speedup 1.0000x reference)
#include <cuda_runtime.h>
#include <cuda_fp16.h>
#include <cstdint>

#define SEQ    4096
#define DMODEL 512
#define NH     8
#define HD     64
#define KDIM   512
#define NW     (SEQ / 32)   // 128 mask words per row

#define BM 128
#define BN 64
#define NKB (SEQ / BN)

// 0.125 * log2(e): folded into Q projection so flash does exp2(S) directly
#define QSCALE 0.18033688011112042f

// ---------------- scratch (device globals; no allocation allowed) ----------------
__device__ __half   g_Xh[SEQ * KDIM];          // fp16 copy of x
__device__ __half   g_Wh[4 * DMODEL * KDIM];   // wq, wk, wv, dense (fp16)
__device__ __half   g_Qh[SEQ * DMODEL];        // pre-scaled by QSCALE
__device__ __half   g_Kh[SEQ * DMODEL];
__device__ __half   g_Vh[SEQ * DMODEL];
__device__ __half   g_Ch[SEQ * DMODEL];        // context (head-major), fp16
__device__ unsigned g_mb[SEQ * NW];

// ================= helpers =================
__device__ __forceinline__ uint32_t smem_u32(const void* p) {
    uint32_t a;
    asm("{ .reg .u64 t; cvta.to.shared.u64 t, %1; cvt.u32.u64 %0, t; }" : "=r"(a) : "l"(p));
    return a;
}
__device__ __forceinline__ void cp16(uint32_t dst, const void* src) {
    asm volatile("cp.async.cg.shared.global [%0], [%1], 16;" :: "r"(dst), "l"(src));
}
__device__ __forceinline__ void cp_commit() { asm volatile("cp.async.commit_group;"); }
__device__ __forceinline__ void cp_wait0()  { asm volatile("cp.async.wait_group 0;" ::: "memory"); }
__device__ __forceinline__ void cp_wait1()  { asm volatile("cp.async.wait_group 1;" ::: "memory"); }

__device__ __forceinline__ void ldsm4(uint32_t* r, uint32_t addr) {
    asm volatile("ldmatrix.sync.aligned.m8n8.x4.shared.b16 {%0,%1,%2,%3}, [%4];"
        : "=r"(r[0]), "=r"(r[1]), "=r"(r[2]), "=r"(r[3]) : "r"(addr));
}
__device__ __forceinline__ void ldsm4t(uint32_t* r, uint32_t addr) {
    asm volatile("ldmatrix.sync.aligned.m8n8.x4.trans.shared.b16 {%0,%1,%2,%3}, [%4];"
        : "=r"(r[0]), "=r"(r[1]), "=r"(r[2]), "=r"(r[3]) : "r"(addr));
}
// D = A*B + D   (m16n8k16, f16 in, f32 accum)
__device__ __forceinline__ void mma16816(float* d, const uint32_t* a, const uint32_t* b) {
    asm volatile("mma.sync.aligned.m16n8k16.row.col.f32.f16.f16.f32 "
        "{%0,%1,%2,%3}, {%4,%5,%6,%7}, {%8,%9}, {%0,%1,%2,%3};"
        : "+f"(d[0]), "+f"(d[1]), "+f"(d[2]), "+f"(d[3])
        : "r"(a[0]), "r"(a[1]), "r"(a[2]), "r"(a[3]), "r"(b[0]), "r"(b[1]));
}
__device__ __forceinline__ uint32_t pack_h2(float a, float b) {
    __half2 h = __floats2half2_rn(a, b);
    return *reinterpret_cast<uint32_t*>(&h);
}
// 2^x on the MUFU pipe
__device__ __forceinline__ float ex2(float x) {
    float y;
    asm("ex2.approx.ftz.f32 %0, %1;" : "=f"(y) : "f"(x));
    return y;
}

// ---------------- convert: x + 4 weight matrices -> fp16 ----------------
__global__ __launch_bounds__(256) void convert_kernel(
    const float* __restrict__ x,  const float* __restrict__ wq,
    const float* __restrict__ wk, const float* __restrict__ wv,
    const float* __restrict__ dw)
{
    int f4 = blockIdx.x * 256 + threadIdx.x;   // 0 .. 786431
    const float4* src; __half* dst; int off;
    if (f4 < 524288) { src = (const float4*)x; off = f4; dst = g_Xh; }
    else {
        int t = f4 - 524288;
        int w = t >> 16; off = t & 65535;
        src = (const float4*)(w == 0 ? wq : w == 1 ? wk : w == 2 ? wv : dw);
        dst = g_Wh + w * (DMODEL * KDIM);
    }
    float4 v = src[off];
    uint2 u = { pack_h2(v.x, v.y), pack_h2(v.z, v.w) };
    *reinterpret_cast<uint2*>(dst + off * 4) = u;
}

// ---------------- HMMA GEMM: out = (A @ W^T + bias) * scale ----------------
// QKV instantiation also carries the mask-pack slice at blockIdx.z == 3:
// 128 CTAs grid-stride the 4096x4096 int32 mask into the 2MB bitmask, running
// CONCURRENTLY with the GEMM CTAs (GEMM is compute-bound, mask is HBM-bound).
#define GP 40

template<bool DENSE>
__global__ __launch_bounds__(256) void hmma_gemm_kernel(
    float* __restrict__ outf, const float* __restrict__ dense_b,
    const float* __restrict__ bq, const float* __restrict__ bk,
    const float* __restrict__ bv, const int* __restrict__ mk)
{
    const int tid = threadIdx.x;

    if (!DENSE && blockIdx.z == 3) {
        // ---- mask pack slice ----
        const int c  = blockIdx.y * gridDim.x + blockIdx.x;   // 0..127
        const int t0 = c * 256 + tid;                         // 0..32767
        const int stride = 128 * 256;
        const int lane = tid & 31;
        #pragma unroll 4
        for (int k = 0; k < 512; k++) {
            int gid = t0 + k * stride;
            int v = mk[gid];
            unsigned b = __ballot_sync(0xffffffffu, v != 0);
            if (lane == 0) g_mb[gid >> 5] = b;
        }
        return;
    }

    __shared__ __half sA[2][128 * GP];
    __shared__ __half sB[2][128 * GP];

    const int lane = tid & 31, wid = tid >> 5;
    const int wm = wid & 1, wn = wid >> 1;
    const int m0 = blockIdx.y * 128, n0 = blockIdx.x * 128;
    const int z = DENSE ? 3 : blockIdx.z;

    const __half* W = g_Wh + z * (DMODEL * KDIM);
    const float* bias = DENSE ? dense_b : (z == 0 ? bq : z == 1 ? bk : bv);
    __half* outh = DENSE ? nullptr : (z == 0 ? g_Qh : z == 1 ? g_Kh : g_Vh);
    const float scale = (!DENSE && z == 0) ? QSCALE : 1.0f;

    const uint32_t sbA = smem_u32(sA), sbB = smem_u32(sB);

    float acc[4][4][4];
    #pragma unroll
    for (int mi = 0; mi < 4; mi++)
        #pragma unroll
        for (int g = 0; g < 4; g++)
            #pragma unroll
            for (int e = 0; e < 4; e++) acc[mi][g][e] = 0.0f;

    const uint32_t abase = ((((lane >> 3) & 1) * 8 + (lane & 7)) * GP) * 2 + ((lane >> 4) & 1) * 16;
    const uint32_t kbase = ((((lane >> 4) & 1) * 8 + (lane & 7)) * GP) * 2 + ((lane >> 3) & 1) * 16;

    #define LOAD_STAGE(kt, buf) do {                                                        \
        const int k0_ = (kt) * 32;                                                          \
        _Pragma("unroll")                                                                   \
        for (int l = 0; l < 2; l++) {                                                       \
            int idx = tid + l * 256;                                                        \
            int r = idx >> 2, c = idx & 3;                                                  \
            const __half* asrc = DENSE                                                      \
                ? (g_Ch + (k0_ >> 6) * (SEQ * HD) + (m0 + r) * HD + (k0_ & 63) + c * 8)     \
                : (g_Xh + (m0 + r) * KDIM + k0_ + c * 8);                                   \
            cp16(sbA + ((buf) * 128 * GP + r * GP) * 2 + c * 16, asrc);                     \
            cp16(sbB + ((buf) * 128 * GP + r * GP) * 2 + c * 16,                            \
                 W + (n0 + r) * KDIM + k0_ + c * 8);                                        \
        }                                                                                   \
        cp_commit();                                                                        \
    } while (0)

    LOAD_STAGE(0, 0);

    for (int kt = 0; kt < KDIM / 32; kt++) {
        const int buf = kt & 1;
        if (kt + 1 < KDIM / 32) { LOAD_STAGE(kt + 1, buf ^ 1); cp_wait1(); }
        else cp_wait0();
        __syncthreads();

        const uint32_t aw = sbA + (buf * 128 * GP + wm * 64 * GP) * 2;
        const uint32_t bw = sbB + (buf * 128 * GP + wn * 32 * GP) * 2;
        #pragma unroll
        for (int t = 0; t < 2; t++) {
            uint32_t Af[4][4];
            #pragma unroll
            for (int mi = 0; mi < 4; mi++)
                ldsm4(Af[mi], aw + (mi * 16 * GP) * 2 + t * 32 + abase);
            uint32_t Bf[2][4];
            #pragma unroll
            for (int bi = 0; bi < 2; bi++)
                ldsm4(Bf[bi], bw + (bi * 16 * GP) * 2 + t * 32 + kbase);
            #pragma unroll
            for (int mi = 0; mi < 4; mi++)
                #pragma unroll
                for (int bi = 0; bi < 2; bi++) {
                    mma16816(acc[mi][bi * 2],     Af[mi], Bf[bi]);
                    mma16816(acc[mi][bi * 2 + 1], Af[mi], Bf[bi] + 2);
                }
        }
        __syncthreads();
    }
    #undef LOAD_STAGE

    const int qr = lane >> 2, qc = (lane & 3) << 1;
    #pragma unroll
    for (int mi = 0; mi < 4; mi++) {
        int mrow = m0 + wm * 64 + mi * 16 + qr;
        #pragma unroll
        for (int g = 0; g < 4; g++) {
            int n = n0 + wn * 32 + g * 8 + qc;
            float b0 = bias[n], b1 = bias[n + 1];
            if (DENSE) {
                float2 u0 = { acc[mi][g][0] + b0, acc[mi][g][1] + b1 };
                float2 u1 = { acc[mi][g][2] + b0, acc[mi][g][3] + b1 };
                *reinterpret_cast<float2*>(outf + mrow * DMODEL + n)       = u0;
                *reinterpret_cast<float2*>(outf + (mrow + 8) * DMODEL + n) = u1;
            } else {
                uint32_t u0 = pack_h2((acc[mi][g][0] + b0) * scale, (acc[mi][g][1] + b1) * scale);
                uint32_t u1 = pack_h2((acc[mi][g][2] + b0) * scale, (acc[mi][g][3] + b1) * scale);
                *reinterpret_cast<uint32_t*>(outh + mrow * DMODEL + n)       = u0;
                *reinterpret_cast<uint32_t*>(outh + (mrow + 8) * DMODEL + n) = u1;
            }
        }
    }
}

// ---------------- fp16 mma.sync flash attention (pipelined, 32 q-rows/warp) ----------------
// BM=128, 128 threads (4 warps x 32 q-rows = 2 row-tiles each), 2 CTAs/SM.
// Each B-fragment (K or V) loaded once per warp feeds BOTH row-tiles (8 MMAs)
// -> halves ldmatrix smem traffic per flop vs 16-row warps.
#define QPITCH 144
#define OFF_Q   0
#define OFF_K0  (128 * QPITCH)
#define OFF_K1  (OFF_K0 + 64 * QPITCH)
#define OFF_V0  (OFF_K1 + 64 * QPITCH)
#define OFF_V1  (OFF_V0 + 64 * QPITCH)
#define FL_SMEM (OFF_V1 + 64 * QPITCH)         // (128+4*64)*144 = 55296 B

__global__ void __launch_bounds__(128, 2) flash_mma_kernel()
{
    extern __shared__ __align__(128) char smem[];
    const uint32_t sb = smem_u32(smem);
    const int tid  = threadIdx.x;
    const int wid  = tid >> 5;
    const int lane = tid & 31;
    const int h    = blockIdx.y;
    const int q0   = blockIdx.x * BM;
    const __half* Qg = g_Qh + h * (SEQ * HD);
    const __half* Kg = g_Kh + h * (SEQ * HD);
    const __half* Vg = g_Vh + h * (SEQ * HD);

    // ---- prologue: Q -> smem (padded); K0,V0 (group), K1 (group) ----
    {
        int r = tid;                              // 128 rows, one per thread
        const uint4* src = reinterpret_cast<const uint4*>(Qg + (q0 + r) * HD);
        char* dst = smem + OFF_Q + r * QPITCH;
        #pragma unroll
        for (int k = 0; k < 8; k++)
            reinterpret_cast<uint4*>(dst)[k] = src[k];
    }
    #pragma unroll
    for (int l = 0; l < 4; l++) {
        int idx = tid + l * 128;                  // 0..511
        int r = idx >> 3, ch = (idx & 7) << 3;
        cp16(sb + OFF_K0 + r * QPITCH + ch * 2, Kg + r * HD + ch);
        cp16(sb + OFF_V0 + r * QPITCH + ch * 2, Vg + r * HD + ch);
    }
    cp_commit();
    #pragma unroll
    for (int l = 0; l < 4; l++) {
        int idx = tid + l * 128;
        int r = idx >> 3, ch = (idx & 7) << 3;
        cp16(sb + OFF_K1 + r * QPITCH + ch * 2, Kg + BN * HD + r * HD + ch);
    }
    cp_commit();
    cp_wait0();
    __syncthreads();

    const int qb = wid * 32;
    const uint32_t abase = ((((lane >> 3) & 1) * 8 + (lane & 7)) * QPITCH) + (((lane >> 4) & 1) * 16);
    const uint32_t kbase = ((((lane >> 4) & 1) * 8 + (lane & 7)) * QPITCH) + (((lane >> 3) & 1) * 16);

    uint32_t Aq[2][4][4];
    #pragma unroll
    for (int u = 0; u < 2; u++)
        #pragma unroll
        for (int t = 0; t < 4; t++)
            ldsm4(Aq[u][t], sb + OFF_Q + (qb + u * 16) * QPITCH + t * 32 + abase);

    float Oacc[2][8][4];
    #pragma unroll
    for (int u = 0; u < 2; u++)
        #pragma unroll
        for (int j = 0; j < 8; j++)
            #pragma unroll
            for (int e = 0; e < 4; e++) Oacc[u][j][e] = 0.0f;

    // ---- issue QK(0) from Kbuf0 (B-frag shared across both row-tiles) ----
    float S[2][8][4];
    #pragma unroll
    for (int u = 0; u < 2; u++)
        #pragma unroll
        for (int j = 0; j < 8; j++)
            #pragma unroll
            for (int e = 0; e < 4; e++) S[u][j][e] = 0.0f;
    #pragma unroll
    for (int jp = 0; jp < 4; jp++) {
        #pragma unroll
        for (int t = 0; t < 4; t++) {
            uint32_t B[4];
            ldsm4(B, sb + OFF_K0 + jp * (16 * QPITCH) + t * 32 + kbase);
            #pragma unroll
            for (int u = 0; u < 2; u++) {
                mma16816(S[u][2 * jp],     Aq[u][t], B);
                mma16816(S[u][2 * jp + 1], Aq[u][t], B + 2);
            }
        }
    }
    __syncthreads();   // LDSM(K0) done in all warps before iter-0 prefetch overwrites Kbuf0

    const int rowb = q0 + qb + (lane >> 2);
    const int qv = lane & 3;
    float lsum[2][2] = { {0.0f, 0.0f}, {0.0f, 0.0f} };

    for (int i = 0; i < NKB; i++) {
        // --- prefetch K(i+2) -> kbuf[i&1], V(i+1) -> vbuf[(i+1)&1] ---
        if (i + 2 < NKB) {
            const uint32_t kn = sb + ((i & 1) ? OFF_K1 : OFF_K0);
            const __half* Kn = Kg + (i + 2) * BN * HD;
            #pragma unroll
            for (int l = 0; l < 4; l++) {
                int idx = tid + l * 128;
                int r = idx >> 3, ch = (idx & 7) << 3;
                cp16(kn + r * QPITCH + ch * 2, Kn + r * HD + ch);
            }
            cp_commit();
        }
        if (i + 1 < NKB) {
            const uint32_t vn = sb + (((i + 1) & 1) ? OFF_V1 : OFF_V0);
            const __half* Vn = Vg + (i + 1) * BN * HD;
            #pragma unroll
            for (int l = 0; l < 4; l++) {
                int idx = tid + l * 128;
                int r = idx >> 3, ch = (idx & 7) << 3;
                cp16(vn + r * QPITCH + ch * 2, Vn + r * HD + ch);
            }
            cp_commit();
        }

        // --- softmax(i) per row-tile: e = masked ? 0 : exp2(S) (MUFU pipe) ---
        uint32_t Ap[2][4][4];
        #pragma unroll
        for (int u = 0; u < 2; u++) {
            uint2 m0 = *reinterpret_cast<const uint2*>(g_mb + (rowb + u * 16)     * NW + (i << 1));
            uint2 m1 = *reinterpret_cast<const uint2*>(g_mb + (rowb + u * 16 + 8) * NW + (i << 1));
            #pragma unroll
            for (int j = 0; j < 8; j++) {
                unsigned w0 = (j < 4) ? m0.x : m0.y;
                unsigned w1 = (j < 4) ? m1.x : m1.y;
                int p0 = ((j & 3) << 3) + (qv << 1);
                float e0 = ((w0 >> p0) & 1u)       ? 0.0f : ex2(S[u][j][0]);
                float e1 = ((w0 >> (p0 + 1)) & 1u) ? 0.0f : ex2(S[u][j][1]);
                float e2 = ((w1 >> p0) & 1u)       ? 0.0f : ex2(S[u][j][2]);
                float e3 = ((w1 >> (p0 + 1)) & 1u) ? 0.0f : ex2(S[u][j][3]);
                lsum[u][0] += e0 + e1;
                lsum[u][1] += e2 + e3;
                int t = j >> 1;
                if ((j & 1) == 0) { Ap[u][t][0] = pack_h2(e0, e1); Ap[u][t][1] = pack_h2(e2, e3); }
                else              { Ap[u][t][2] = pack_h2(e0, e1); Ap[u][t][3] = pack_h2(e2, e3); }
            }
        }

        // --- fused MMA issue: QK(i+1) + PV(i), B-frags reused across row-tiles ---
        const uint32_t vcur = sb + ((i & 1) ? OFF_V1 : OFF_V0);
        if (i + 1 < NKB) {
            const uint32_t kcur = sb + (((i + 1) & 1) ? OFF_K1 : OFF_K0);
            #pragma unroll
            for (int u = 0; u < 2; u++)
                #pragma unroll
                for (int j = 0; j < 8; j++)
                    #pragma unroll
                    for (int e = 0; e < 4; e++) S[u][j][e] = 0.0f;
            #pragma unroll
            for (int jp = 0; jp < 4; jp++) {
                #pragma unroll
                for (int t = 0; t < 4; t++) {
                    uint32_t Bk[4];
                    ldsm4(Bk, kcur + jp * (16 * QPITCH) + t * 32 + kbase);
                    uint32_t Bv[4];
                    ldsm4t(Bv, vcur + t * (16 * QPITCH) + jp * 32 + abase);
                    #pragma unroll
                    for (int u = 0; u < 2; u++) {
                        mma16816(S[u][2 * jp],        Aq[u][t], Bk);
                        mma16816(S[u][2 * jp + 1],    Aq[u][t], Bk + 2);
                        mma16816(Oacc[u][2 * jp],     Ap[u][t], Bv);
                        mma16816(Oacc[u][2 * jp + 1], Ap[u][t], Bv + 2);
                    }
                }
            }
        } else {
            #pragma unroll
            for (int jp = 0; jp < 4; jp++) {
                #pragma unroll
                for (int t = 0; t < 4; t++) {
                    uint32_t Bv[4];
                    ldsm4t(Bv, vcur + t * (16 * QPITCH) + jp * 32 + abase);
                    #pragma unroll
                    for (int u = 0; u < 2; u++) {
                        mma16816(Oacc[u][2 * jp],     Ap[u][t], Bv);
                        mma16816(Oacc[u][2 * jp + 1], Ap[u][t], Bv + 2);
                    }
                }
            }
        }

        cp_wait0();
        __syncthreads();
    }

    // ---- epilogue ----
    #pragma unroll
    for (int u = 0; u < 2; u++) {
        float l0 = lsum[u][0], l1 = lsum[u][1];
        l0 += __shfl_xor_sync(0xffffffffu, l0, 1);
        l0 += __shfl_xor_sync(0xffffffffu, l0, 2);
        l1 += __shfl_xor_sync(0xffffffffu, l1, 1);
        l1 += __shfl_xor_sync(0xffffffffu, l1, 2);
        float inv0 = 1.0f / l0;
        float inv1 = 1.0f / l1;

        __half* C0 = g_Ch + h * (SEQ * HD) + (rowb + u * 16) * HD;
        __half* C1 = C0 + 8 * HD;
        #pragma unroll
        for (int j = 0; j < 8; j++) {
            int c = 8 * j + (qv << 1);
            *reinterpret_cast<uint32_t*>(C0 + c) = pack_h2(Oacc[u][j][0] * inv0, Oacc[u][j][1] * inv0);
            *reinterpret_cast<uint32_t*>(C1 + c) = pack_h2(Oacc[u][j][2] * inv1, Oacc[u][j][3] * inv1);
        }
    }
}

// ---------------- launch ----------------
extern "C" void kernel_launch(void* const* d_in, const int* in_sizes, int n_in,
                              void* d_out, int out_size)
{
    (void)in_sizes; (void)n_in; (void)out_size;
    const float* x  = (const float*)d_in[0];
    const int*   mk = (const int*)d_in[1];
    const float* wq = (const float*)d_in[2];
    const float* bq = (const float*)d_in[3];
    const float* wk = (const float*)d_in[4];
    const float* bk = (const float*)d_in[5];
    const float* wv = (const float*)d_in[6];
    const float* bv = (const float*)d_in[7];
    const float* dw = (const float*)d_in[8];
    const float* db = (const float*)d_in[9];
    float* out = (float*)d_out;

    cudaFuncSetAttribute(flash_mma_kernel,
                         cudaFuncAttributeMaxDynamicSharedMemorySize, FL_SMEM);

    convert_kernel<<<3072, 256>>>(x, wq, wk, wv, dw);
    // z = 0..2: Q/K/V GEMMs; z = 3: concurrent mask pack (memory-bound, hides
    // under the compute-bound GEMM CTAs)
    hmma_gemm_kernel<false><<<dim3(DMODEL / 128, SEQ / 128, 4), 256>>>(
        nullptr, nullptr, bq, bk, bv, mk);
    flash_mma_kernel<<<dim3(SEQ / BM, NH), 128, FL_SMEM>>>();
    hmma_gemm_kernel<true><<<dim3(DMODEL / 128, SEQ / 128), 256>>>(
        out, db, nullptr, nullptr, nullptr, nullptr);
}

// round 14
// speedup vs baseline: 1.3591x; 1.3591x over previous
#include <cuda_runtime.h>
#include <cuda_fp16.h>
#include <cstdint>

#define SEQ    4096
#define DMODEL 512
#define NH     8
#define HD     64
#define KDIM   512
#define NW     (SEQ / 32)   // 128 mask words per row

#define BM 128
#define BN 64
#define NKB (SEQ / BN)

// 0.125 * log2(e): folded into Q projection so flash does exp2(S) directly
#define QSCALE 0.18033688011112042f

// ---------------- scratch (device globals; no allocation allowed) ----------------
__device__ __half   g_Xh[SEQ * KDIM];          // fp16 copy of x
__device__ __half   g_Wh[4 * DMODEL * KDIM];   // wq, wk, wv, dense (fp16)
__device__ __half   g_Qh[SEQ * DMODEL];        // pre-scaled by QSCALE
__device__ __half   g_Kh[SEQ * DMODEL];
__device__ __half   g_Vh[SEQ * DMODEL];
__device__ __half   g_Ch[SEQ * DMODEL];        // context (head-major), fp16
__device__ unsigned g_mb[SEQ * NW];

// ================= helpers =================
__device__ __forceinline__ uint32_t smem_u32(const void* p) {
    uint32_t a;
    asm("{ .reg .u64 t; cvta.to.shared.u64 t, %1; cvt.u32.u64 %0, t; }" : "=r"(a) : "l"(p));
    return a;
}
__device__ __forceinline__ void cp16(uint32_t dst, const void* src) {
    asm volatile("cp.async.cg.shared.global [%0], [%1], 16;" :: "r"(dst), "l"(src));
}
__device__ __forceinline__ void cp_commit() { asm volatile("cp.async.commit_group;"); }
__device__ __forceinline__ void cp_wait0()  { asm volatile("cp.async.wait_group 0;" ::: "memory"); }
__device__ __forceinline__ void cp_wait1()  { asm volatile("cp.async.wait_group 1;" ::: "memory"); }

__device__ __forceinline__ void ldsm4(uint32_t* r, uint32_t addr) {
    asm volatile("ldmatrix.sync.aligned.m8n8.x4.shared.b16 {%0,%1,%2,%3}, [%4];"
        : "=r"(r[0]), "=r"(r[1]), "=r"(r[2]), "=r"(r[3]) : "r"(addr));
}
__device__ __forceinline__ void ldsm4t(uint32_t* r, uint32_t addr) {
    asm volatile("ldmatrix.sync.aligned.m8n8.x4.trans.shared.b16 {%0,%1,%2,%3}, [%4];"
        : "=r"(r[0]), "=r"(r[1]), "=r"(r[2]), "=r"(r[3]) : "r"(addr));
}
// D = A*B + D   (m16n8k16, f16 in, f32 accum)
__device__ __forceinline__ void mma16816(float* d, const uint32_t* a, const uint32_t* b) {
    asm volatile("mma.sync.aligned.m16n8k16.row.col.f32.f16.f16.f32 "
        "{%0,%1,%2,%3}, {%4,%5,%6,%7}, {%8,%9}, {%0,%1,%2,%3};"
        : "+f"(d[0]), "+f"(d[1]), "+f"(d[2]), "+f"(d[3])
        : "r"(a[0]), "r"(a[1]), "r"(a[2]), "r"(a[3]), "r"(b[0]), "r"(b[1]));
}
__device__ __forceinline__ uint32_t pack_h2(float a, float b) {
    __half2 h = __floats2half2_rn(a, b);
    return *reinterpret_cast<uint32_t*>(&h);
}
// 2^x on the MUFU pipe
__device__ __forceinline__ float ex2(float x) {
    float y;
    asm("ex2.approx.ftz.f32 %0, %1;" : "=f"(y) : "f"(x));
    return y;
}

// ---------------- convert (x + weights -> fp16) + mask pack, one launch ----------------
// blocks [0, 3072): float4 convert of x (2M elems) + 4 weight matrices (1M elems)
// blocks [3072, 3072+16384): mask pack; each thread loads uint4 (4 ints), builds a
// nibble, 3-step shuffle combine -> one 32-bit mask word per 8 lanes.
__global__ __launch_bounds__(256) void convert_mask_kernel(
    const float* __restrict__ x,  const float* __restrict__ wq,
    const float* __restrict__ wk, const float* __restrict__ wv,
    const float* __restrict__ dw, const int* __restrict__ mk)
{
    const int tid = threadIdx.x;
    if (blockIdx.x < 3072) {
        int f4 = blockIdx.x * 256 + tid;   // 0 .. 786431
        const float4* src; __half* dst; int off;
        if (f4 < 524288) { src = (const float4*)x; off = f4; dst = g_Xh; }
        else {
            int t = f4 - 524288;
            int w = t >> 16; off = t & 65535;
            src = (const float4*)(w == 0 ? wq : w == 1 ? wk : w == 2 ? wv : dw);
            dst = g_Wh + w * (DMODEL * KDIM);
        }
        float4 v = src[off];
        uint2 u = { pack_h2(v.x, v.y), pack_h2(v.z, v.w) };
        *reinterpret_cast<uint2*>(dst + off * 4) = u;
    } else {
        const int base = (blockIdx.x - 3072) * 1024;     // int index, 1024 ints/CTA
        uint4 v = *reinterpret_cast<const uint4*>(mk + base + tid * 4);
        unsigned n = (v.x != 0 ? 1u : 0u) | (v.y != 0 ? 2u : 0u)
                   | (v.z != 0 ? 4u : 0u) | (v.w != 0 ? 8u : 0u);
        n |= __shfl_xor_sync(0xffffffffu, n, 1) << 4;    // valid at lanes %2==0
        n |= __shfl_xor_sync(0xffffffffu, n, 2) << 8;    // valid at lanes %4==0
        n |= __shfl_xor_sync(0xffffffffu, n, 4) << 16;   // valid at lanes %8==0
        if ((tid & 7) == 0)
            g_mb[(base >> 5) + (tid >> 3)] = n;
    }
}

// ---------------- HMMA GEMM: out = (A @ W^T + bias) * scale ----------------
// 128x128 tile, BK=64, 256 threads (8 warps as 2x4), cp.async double buffer.
// Row pitch 72 halves (144B) -> conflict-free ldmatrix; 64 MMAs per barrier pair.
#define GGP 72

template<bool DENSE>
__global__ __launch_bounds__(256) void hmma_gemm_kernel(
    float* __restrict__ outf, const float* __restrict__ dense_b,
    const float* __restrict__ bq, const float* __restrict__ bk,
    const float* __restrict__ bv)
{
    __shared__ __half sA[2][128 * GGP];
    __shared__ __half sB[2][128 * GGP];

    const int tid = threadIdx.x, lane = tid & 31, wid = tid >> 5;
    const int wm = wid & 1, wn = wid >> 1;
    const int m0 = blockIdx.y * 128, n0 = blockIdx.x * 128;
    const int z = DENSE ? 3 : blockIdx.z;

    const __half* W = g_Wh + z * (DMODEL * KDIM);
    const float* bias = DENSE ? dense_b : (z == 0 ? bq : z == 1 ? bk : bv);
    __half* outh = DENSE ? nullptr : (z == 0 ? g_Qh : z == 1 ? g_Kh : g_Vh);
    const float scale = (!DENSE && z == 0) ? QSCALE : 1.0f;

    const uint32_t sbA = smem_u32(sA), sbB = smem_u32(sB);

    float acc[4][4][4];
    #pragma unroll
    for (int mi = 0; mi < 4; mi++)
        #pragma unroll
        for (int g = 0; g < 4; g++)
            #pragma unroll
            for (int e = 0; e < 4; e++) acc[mi][g][e] = 0.0f;

    const uint32_t abase = ((((lane >> 3) & 1) * 8 + (lane & 7)) * GGP) * 2 + ((lane >> 4) & 1) * 16;
    const uint32_t kbase = ((((lane >> 4) & 1) * 8 + (lane & 7)) * GGP) * 2 + ((lane >> 3) & 1) * 16;

    // one stage = 128 rows x 64 halves (128B = 8 chunks of 16B) per matrix
    #define LOAD_STAGE(kt, buf) do {                                                        \
        const int k0_ = (kt) * 64;                                                          \
        _Pragma("unroll")                                                                   \
        for (int l = 0; l < 4; l++) {                                                       \
            int idx = tid + l * 256;                                                        \
            int r = idx >> 3, c = idx & 7;                                                  \
            const __half* asrc = DENSE                                                      \
                ? (g_Ch + (k0_ >> 6) * (SEQ * HD) + (m0 + r) * HD + c * 8)                  \
                : (g_Xh + (m0 + r) * KDIM + k0_ + c * 8);                                   \
            cp16(sbA + ((buf) * 128 * GGP + r * GGP) * 2 + c * 16, asrc);                   \
            cp16(sbB + ((buf) * 128 * GGP + r * GGP) * 2 + c * 16,                          \
                 W + (n0 + r) * KDIM + k0_ + c * 8);                                        \
        }                                                                                   \
        cp_commit();                                                                        \
    } while (0)

    LOAD_STAGE(0, 0);

    for (int kt = 0; kt < KDIM / 64; kt++) {
        const int buf = kt & 1;
        if (kt + 1 < KDIM / 64) { LOAD_STAGE(kt + 1, buf ^ 1); cp_wait1(); }
        else cp_wait0();
        __syncthreads();

        const uint32_t aw = sbA + (buf * 128 * GGP + wm * 64 * GGP) * 2;
        const uint32_t bw = sbB + (buf * 128 * GGP + wn * 32 * GGP) * 2;
        #pragma unroll
        for (int t = 0; t < 4; t++) {
            uint32_t Af[4][4];
            #pragma unroll
            for (int mi = 0; mi < 4; mi++)
                ldsm4(Af[mi], aw + (mi * 16 * GGP) * 2 + t * 32 + abase);
            uint32_t Bf[2][4];
            #pragma unroll
            for (int bi = 0; bi < 2; bi++)
                ldsm4(Bf[bi], bw + (bi * 16 * GGP) * 2 + t * 32 + kbase);
            #pragma unroll
            for (int mi = 0; mi < 4; mi++)
                #pragma unroll
                for (int bi = 0; bi < 2; bi++) {
                    mma16816(acc[mi][bi * 2],     Af[mi], Bf[bi]);
                    mma16816(acc[mi][bi * 2 + 1], Af[mi], Bf[bi] + 2);
                }
        }
        __syncthreads();
    }
    #undef LOAD_STAGE

    const int qr = lane >> 2, qc = (lane & 3) << 1;
    #pragma unroll
    for (int mi = 0; mi < 4; mi++) {
        int mrow = m0 + wm * 64 + mi * 16 + qr;
        #pragma unroll
        for (int g = 0; g < 4; g++) {
            int n = n0 + wn * 32 + g * 8 + qc;
            float b0 = bias[n], b1 = bias[n + 1];
            if (DENSE) {
                float2 u0 = { acc[mi][g][0] + b0, acc[mi][g][1] + b1 };
                float2 u1 = { acc[mi][g][2] + b0, acc[mi][g][3] + b1 };
                *reinterpret_cast<float2*>(outf + mrow * DMODEL + n)       = u0;
                *reinterpret_cast<float2*>(outf + (mrow + 8) * DMODEL + n) = u1;
            } else {
                uint32_t u0 = pack_h2((acc[mi][g][0] + b0) * scale, (acc[mi][g][1] + b1) * scale);
                uint32_t u1 = pack_h2((acc[mi][g][2] + b0) * scale, (acc[mi][g][3] + b1) * scale);
                *reinterpret_cast<uint32_t*>(outh + mrow * DMODEL + n)       = u0;
                *reinterpret_cast<uint32_t*>(outh + (mrow + 8) * DMODEL + n) = u1;
            }
        }
    }
}

// ---------------- fp16 mma.sync flash attention (pipelined, 32 q-rows/warp) ----------------
// BM=128, 128 threads (4 warps x 32 q-rows = 2 row-tiles each), 2 CTAs/SM.
#define QPITCH 144
#define OFF_Q   0
#define OFF_K0  (128 * QPITCH)
#define OFF_K1  (OFF_K0 + 64 * QPITCH)
#define OFF_V0  (OFF_K1 + 64 * QPITCH)
#define OFF_V1  (OFF_V0 + 64 * QPITCH)
#define FL_SMEM (OFF_V1 + 64 * QPITCH)         // (128+4*64)*144 = 55296 B

__global__ void __launch_bounds__(128, 2) flash_mma_kernel()
{
    extern __shared__ __align__(128) char smem[];
    const uint32_t sb = smem_u32(smem);
    const int tid  = threadIdx.x;
    const int wid  = tid >> 5;
    const int lane = tid & 31;
    const int h    = blockIdx.y;
    const int q0   = blockIdx.x * BM;
    const __half* Qg = g_Qh + h * (SEQ * HD);
    const __half* Kg = g_Kh + h * (SEQ * HD);
    const __half* Vg = g_Vh + h * (SEQ * HD);

    // ---- prologue: Q -> smem (padded); K0,V0 (group), K1 (group) ----
    {
        int r = tid;                              // 128 rows, one per thread
        const uint4* src = reinterpret_cast<const uint4*>(Qg + (q0 + r) * HD);
        char* dst = smem + OFF_Q + r * QPITCH;
        #pragma unroll
        for (int k = 0; k < 8; k++)
            reinterpret_cast<uint4*>(dst)[k] = src[k];
    }
    #pragma unroll
    for (int l = 0; l < 4; l++) {
        int idx = tid + l * 128;                  // 0..511
        int r = idx >> 3, ch = (idx & 7) << 3;
        cp16(sb + OFF_K0 + r * QPITCH + ch * 2, Kg + r * HD + ch);
        cp16(sb + OFF_V0 + r * QPITCH + ch * 2, Vg + r * HD + ch);
    }
    cp_commit();
    #pragma unroll
    for (int l = 0; l < 4; l++) {
        int idx = tid + l * 128;
        int r = idx >> 3, ch = (idx & 7) << 3;
        cp16(sb + OFF_K1 + r * QPITCH + ch * 2, Kg + BN * HD + r * HD + ch);
    }
    cp_commit();
    cp_wait0();
    __syncthreads();

    const int qb = wid * 32;
    const uint32_t abase = ((((lane >> 3) & 1) * 8 + (lane & 7)) * QPITCH) + (((lane >> 4) & 1) * 16);
    const uint32_t kbase = ((((lane >> 4) & 1) * 8 + (lane & 7)) * QPITCH) + (((lane >> 3) & 1) * 16);

    uint32_t Aq[2][4][4];
    #pragma unroll
    for (int u = 0; u < 2; u++)
        #pragma unroll
        for (int t = 0; t < 4; t++)
            ldsm4(Aq[u][t], sb + OFF_Q + (qb + u * 16) * QPITCH + t * 32 + abase);

    float Oacc[2][8][4];
    #pragma unroll
    for (int u = 0; u < 2; u++)
        #pragma unroll
        for (int j = 0; j < 8; j++)
            #pragma unroll
            for (int e = 0; e < 4; e++) Oacc[u][j][e] = 0.0f;

    // ---- issue QK(0) from Kbuf0 (B-frag shared across both row-tiles) ----
    float S[2][8][4];
    #pragma unroll
    for (int u = 0; u < 2; u++)
        #pragma unroll
        for (int j = 0; j < 8; j++)
            #pragma unroll
            for (int e = 0; e < 4; e++) S[u][j][e] = 0.0f;
    #pragma unroll
    for (int jp = 0; jp < 4; jp++) {
        #pragma unroll
        for (int t = 0; t < 4; t++) {
            uint32_t B[4];
            ldsm4(B, sb + OFF_K0 + jp * (16 * QPITCH) + t * 32 + kbase);
            #pragma unroll
            for (int u = 0; u < 2; u++) {
                mma16816(S[u][2 * jp],     Aq[u][t], B);
                mma16816(S[u][2 * jp + 1], Aq[u][t], B + 2);
            }
        }
    }
    __syncthreads();   // LDSM(K0) done in all warps before iter-0 prefetch overwrites Kbuf0

    const int rowb = q0 + qb + (lane >> 2);
    const int qv = lane & 3;
    float lsum[2][2] = { {0.0f, 0.0f}, {0.0f, 0.0f} };

    for (int i = 0; i < NKB; i++) {
        // --- prefetch K(i+2) -> kbuf[i&1], V(i+1) -> vbuf[(i+1)&1] ---
        if (i + 2 < NKB) {
            const uint32_t kn = sb + ((i & 1) ? OFF_K1 : OFF_K0);
            const __half* Kn = Kg + (i + 2) * BN * HD;
            #pragma unroll
            for (int l = 0; l < 4; l++) {
                int idx = tid + l * 128;
                int r = idx >> 3, ch = (idx & 7) << 3;
                cp16(kn + r * QPITCH + ch * 2, Kn + r * HD + ch);
            }
            cp_commit();
        }
        if (i + 1 < NKB) {
            const uint32_t vn = sb + (((i + 1) & 1) ? OFF_V1 : OFF_V0);
            const __half* Vn = Vg + (i + 1) * BN * HD;
            #pragma unroll
            for (int l = 0; l < 4; l++) {
                int idx = tid + l * 128;
                int r = idx >> 3, ch = (idx & 7) << 3;
                cp16(vn + r * QPITCH + ch * 2, Vn + r * HD + ch);
            }
            cp_commit();
        }

        // --- softmax(i) per row-tile: e = masked ? 0 : exp2(S) (MUFU pipe) ---
        uint32_t Ap[2][4][4];
        #pragma unroll
        for (int u = 0; u < 2; u++) {
            uint2 m0 = *reinterpret_cast<const uint2*>(g_mb + (rowb + u * 16)     * NW + (i << 1));
            uint2 m1 = *reinterpret_cast<const uint2*>(g_mb + (rowb + u * 16 + 8) * NW + (i << 1));
            #pragma unroll
            for (int j = 0; j < 8; j++) {
                unsigned w0 = (j < 4) ? m0.x : m0.y;
                unsigned w1 = (j < 4) ? m1.x : m1.y;
                int p0 = ((j & 3) << 3) + (qv << 1);
                float e0 = ((w0 >> p0) & 1u)       ? 0.0f : ex2(S[u][j][0]);
                float e1 = ((w0 >> (p0 + 1)) & 1u) ? 0.0f : ex2(S[u][j][1]);
                float e2 = ((w1 >> p0) & 1u)       ? 0.0f : ex2(S[u][j][2]);
                float e3 = ((w1 >> (p0 + 1)) & 1u) ? 0.0f : ex2(S[u][j][3]);
                lsum[u][0] += e0 + e1;
                lsum[u][1] += e2 + e3;
                int t = j >> 1;
                if ((j & 1) == 0) { Ap[u][t][0] = pack_h2(e0, e1); Ap[u][t][1] = pack_h2(e2, e3); }
                else              { Ap[u][t][2] = pack_h2(e0, e1); Ap[u][t][3] = pack_h2(e2, e3); }
            }
        }

        // --- fused MMA issue: QK(i+1) + PV(i), B-frags reused across row-tiles ---
        const uint32_t vcur = sb + ((i & 1) ? OFF_V1 : OFF_V0);
        if (i + 1 < NKB) {
            const uint32_t kcur = sb + (((i + 1) & 1) ? OFF_K1 : OFF_K0);
            #pragma unroll
            for (int u = 0; u < 2; u++)
                #pragma unroll
                for (int j = 0; j < 8; j++)
                    #pragma unroll
                    for (int e = 0; e < 4; e++) S[u][j][e] = 0.0f;
            #pragma unroll
            for (int jp = 0; jp < 4; jp++) {
                #pragma unroll
                for (int t = 0; t < 4; t++) {
                    uint32_t Bk[4];
                    ldsm4(Bk, kcur + jp * (16 * QPITCH) + t * 32 + kbase);
                    uint32_t Bv[4];
                    ldsm4t(Bv, vcur + t * (16 * QPITCH) + jp * 32 + abase);
                    #pragma unroll
                    for (int u = 0; u < 2; u++) {
                        mma16816(S[u][2 * jp],        Aq[u][t], Bk);
                        mma16816(S[u][2 * jp + 1],    Aq[u][t], Bk + 2);
                        mma16816(Oacc[u][2 * jp],     Ap[u][t], Bv);
                        mma16816(Oacc[u][2 * jp + 1], Ap[u][t], Bv + 2);
                    }
                }
            }
        } else {
            #pragma unroll
            for (int jp = 0; jp < 4; jp++) {
                #pragma unroll
                for (int t = 0; t < 4; t++) {
                    uint32_t Bv[4];
                    ldsm4t(Bv, vcur + t * (16 * QPITCH) + jp * 32 + abase);
                    #pragma unroll
                    for (int u = 0; u < 2; u++) {
                        mma16816(Oacc[u][2 * jp],     Ap[u][t], Bv);
                        mma16816(Oacc[u][2 * jp + 1], Ap[u][t], Bv + 2);
                    }
                }
            }
        }

        cp_wait0();
        __syncthreads();
    }

    // ---- epilogue ----
    #pragma unroll
    for (int u = 0; u < 2; u++) {
        float l0 = lsum[u][0], l1 = lsum[u][1];
        l0 += __shfl_xor_sync(0xffffffffu, l0, 1);
        l0 += __shfl_xor_sync(0xffffffffu, l0, 2);
        l1 += __shfl_xor_sync(0xffffffffu, l1, 1);
        l1 += __shfl_xor_sync(0xffffffffu, l1, 2);
        float inv0 = 1.0f / l0;
        float inv1 = 1.0f / l1;

        __half* C0 = g_Ch + h * (SEQ * HD) + (rowb + u * 16) * HD;
        __half* C1 = C0 + 8 * HD;
        #pragma unroll
        for (int j = 0; j < 8; j++) {
            int c = 8 * j + (qv << 1);
            *reinterpret_cast<uint32_t*>(C0 + c) = pack_h2(Oacc[u][j][0] * inv0, Oacc[u][j][1] * inv0);
            *reinterpret_cast<uint32_t*>(C1 + c) = pack_h2(Oacc[u][j][2] * inv1, Oacc[u][j][3] * inv1);
        }
    }
}

// ---------------- launch ----------------
extern "C" void kernel_launch(void* const* d_in, const int* in_sizes, int n_in,
                              void* d_out, int out_size)
{
    (void)in_sizes; (void)n_in; (void)out_size;
    const float* x  = (const float*)d_in[0];
    const int*   mk = (const int*)d_in[1];
    const float* wq = (const float*)d_in[2];
    const float* bq = (const float*)d_in[3];
    const float* wk = (const float*)d_in[4];
    const float* bk = (const float*)d_in[5];
    const float* wv = (const float*)d_in[6];
    const float* bv = (const float*)d_in[7];
    const float* dw = (const float*)d_in[8];
    const float* db = (const float*)d_in[9];
    float* out = (float*)d_out;

    cudaFuncSetAttribute(flash_mma_kernel,
                         cudaFuncAttributeMaxDynamicSharedMemorySize, FL_SMEM);

    convert_mask_kernel<<<3072 + 16384, 256>>>(x, wq, wk, wv, dw, mk);
    hmma_gemm_kernel<false><<<dim3(DMODEL / 128, SEQ / 128, 3), 256>>>(nullptr, nullptr, bq, bk, bv);
    flash_mma_kernel<<<dim3(SEQ / BM, NH), 128, FL_SMEM>>>();
    hmma_gemm_kernel<true><<<dim3(DMODEL / 128, SEQ / 128), 256>>>(out, db, nullptr, nullptr, nullptr);
}

// round 15
// speedup vs baseline: 1.4098x; 1.0374x over previous
#include <cuda_runtime.h>
#include <cuda_fp16.h>
#include <cstdint>

#define SEQ    4096
#define DMODEL 512
#define NH     8
#define HD     64
#define KDIM   512
#define NW     (SEQ / 32)   // 128 mask words per row

#define BM 128
#define BN 64
#define NKB (SEQ / BN)

// 0.125 * log2(e): folded into Q projection so flash does exp2(S) directly
#define QSCALE 0.18033688011112042f

// ---------------- scratch (device globals; no allocation allowed) ----------------
__device__ __half   g_Xh[SEQ * KDIM];          // fp16 copy of x
__device__ __half   g_Wh[4 * DMODEL * KDIM];   // wq, wk, wv, dense (fp16)
__device__ __half   g_Qh[SEQ * DMODEL];        // pre-scaled by QSCALE
__device__ __half   g_Kh[SEQ * DMODEL];
__device__ __half   g_Vh[SEQ * DMODEL];
__device__ __half   g_Ch[SEQ * DMODEL];        // context (head-major), fp16
__device__ unsigned g_mb[SEQ * NW];

// ================= helpers =================
__device__ __forceinline__ uint32_t smem_u32(const void* p) {
    uint32_t a;
    asm("{ .reg .u64 t; cvta.to.shared.u64 t, %1; cvt.u32.u64 %0, t; }" : "=r"(a) : "l"(p));
    return a;
}
__device__ __forceinline__ void cp16(uint32_t dst, const void* src) {
    asm volatile("cp.async.cg.shared.global [%0], [%1], 16;" :: "r"(dst), "l"(src));
}
__device__ __forceinline__ void cp_commit() { asm volatile("cp.async.commit_group;"); }
__device__ __forceinline__ void cp_wait0()  { asm volatile("cp.async.wait_group 0;" ::: "memory"); }
__device__ __forceinline__ void cp_wait1()  { asm volatile("cp.async.wait_group 1;" ::: "memory"); }

__device__ __forceinline__ void ldsm4(uint32_t* r, uint32_t addr) {
    asm volatile("ldmatrix.sync.aligned.m8n8.x4.shared.b16 {%0,%1,%2,%3}, [%4];"
        : "=r"(r[0]), "=r"(r[1]), "=r"(r[2]), "=r"(r[3]) : "r"(addr));
}
__device__ __forceinline__ void ldsm4t(uint32_t* r, uint32_t addr) {
    asm volatile("ldmatrix.sync.aligned.m8n8.x4.trans.shared.b16 {%0,%1,%2,%3}, [%4];"
        : "=r"(r[0]), "=r"(r[1]), "=r"(r[2]), "=r"(r[3]) : "r"(addr));
}
// D = A*B + D   (m16n8k16, f16 in, f32 accum)
__device__ __forceinline__ void mma16816(float* d, const uint32_t* a, const uint32_t* b) {
    asm volatile("mma.sync.aligned.m16n8k16.row.col.f32.f16.f16.f32 "
        "{%0,%1,%2,%3}, {%4,%5,%6,%7}, {%8,%9}, {%0,%1,%2,%3};"
        : "+f"(d[0]), "+f"(d[1]), "+f"(d[2]), "+f"(d[3])
        : "r"(a[0]), "r"(a[1]), "r"(a[2]), "r"(a[3]), "r"(b[0]), "r"(b[1]));
}
__device__ __forceinline__ uint32_t pack_h2(float a, float b) {
    __half2 h = __floats2half2_rn(a, b);
    return *reinterpret_cast<uint32_t*>(&h);
}
// 2^x on the MUFU pipe
__device__ __forceinline__ float ex2(float x) {
    float y;
    asm("ex2.approx.ftz.f32 %0, %1;" : "=f"(y) : "f"(x));
    return y;
}

// ---------------- convert (x + weights -> fp16) + mask pack, one launch ----------------
__global__ __launch_bounds__(256) void convert_mask_kernel(
    const float* __restrict__ x,  const float* __restrict__ wq,
    const float* __restrict__ wk, const float* __restrict__ wv,
    const float* __restrict__ dw, const int* __restrict__ mk)
{
    const int tid = threadIdx.x;
    if (blockIdx.x < 3072) {
        int f4 = blockIdx.x * 256 + tid;   // 0 .. 786431
        const float4* src; __half* dst; int off;
        if (f4 < 524288) { src = (const float4*)x; off = f4; dst = g_Xh; }
        else {
            int t = f4 - 524288;
            int w = t >> 16; off = t & 65535;
            src = (const float4*)(w == 0 ? wq : w == 1 ? wk : w == 2 ? wv : dw);
            dst = g_Wh + w * (DMODEL * KDIM);
        }
        float4 v = src[off];
        uint2 u = { pack_h2(v.x, v.y), pack_h2(v.z, v.w) };
        *reinterpret_cast<uint2*>(dst + off * 4) = u;
    } else {
        const int base = (blockIdx.x - 3072) * 1024;     // int index, 1024 ints/CTA
        uint4 v = *reinterpret_cast<const uint4*>(mk + base + tid * 4);
        unsigned n = (v.x != 0 ? 1u : 0u) | (v.y != 0 ? 2u : 0u)
                   | (v.z != 0 ? 4u : 0u) | (v.w != 0 ? 8u : 0u);
        n |= __shfl_xor_sync(0xffffffffu, n, 1) << 4;    // valid at lanes %2==0
        n |= __shfl_xor_sync(0xffffffffu, n, 2) << 8;    // valid at lanes %4==0
        n |= __shfl_xor_sync(0xffffffffu, n, 4) << 16;   // valid at lanes %8==0
        if ((tid & 7) == 0)
            g_mb[(base >> 5) + (tid >> 3)] = n;
    }
}

// ---------------- HMMA GEMM: out = (A @ W^T + bias) * scale ----------------
// 128x128 tile, BK=64, 256 threads (8 warps as 2x4), cp.async double buffer.
#define GGP 72

template<bool DENSE>
__global__ __launch_bounds__(256) void hmma_gemm_kernel(
    float* __restrict__ outf, const float* __restrict__ dense_b,
    const float* __restrict__ bq, const float* __restrict__ bk,
    const float* __restrict__ bv)
{
    __shared__ __half sA[2][128 * GGP];
    __shared__ __half sB[2][128 * GGP];

    const int tid = threadIdx.x, lane = tid & 31, wid = tid >> 5;
    const int wm = wid & 1, wn = wid >> 1;
    const int m0 = blockIdx.y * 128, n0 = blockIdx.x * 128;
    const int z = DENSE ? 3 : blockIdx.z;

    const __half* W = g_Wh + z * (DMODEL * KDIM);
    const float* bias = DENSE ? dense_b : (z == 0 ? bq : z == 1 ? bk : bv);
    __half* outh = DENSE ? nullptr : (z == 0 ? g_Qh : z == 1 ? g_Kh : g_Vh);
    const float scale = (!DENSE && z == 0) ? QSCALE : 1.0f;

    const uint32_t sbA = smem_u32(sA), sbB = smem_u32(sB);

    float acc[4][4][4];
    #pragma unroll
    for (int mi = 0; mi < 4; mi++)
        #pragma unroll
        for (int g = 0; g < 4; g++)
            #pragma unroll
            for (int e = 0; e < 4; e++) acc[mi][g][e] = 0.0f;

    const uint32_t abase = ((((lane >> 3) & 1) * 8 + (lane & 7)) * GGP) * 2 + ((lane >> 4) & 1) * 16;
    const uint32_t kbase = ((((lane >> 4) & 1) * 8 + (lane & 7)) * GGP) * 2 + ((lane >> 3) & 1) * 16;

    #define LOAD_STAGE(kt, buf) do {                                                        \
        const int k0_ = (kt) * 64;                                                          \
        _Pragma("unroll")                                                                   \
        for (int l = 0; l < 4; l++) {                                                       \
            int idx = tid + l * 256;                                                        \
            int r = idx >> 3, c = idx & 7;                                                  \
            const __half* asrc = DENSE                                                      \
                ? (g_Ch + (k0_ >> 6) * (SEQ * HD) + (m0 + r) * HD + c * 8)                  \
                : (g_Xh + (m0 + r) * KDIM + k0_ + c * 8);                                   \
            cp16(sbA + ((buf) * 128 * GGP + r * GGP) * 2 + c * 16, asrc);                   \
            cp16(sbB + ((buf) * 128 * GGP + r * GGP) * 2 + c * 16,                          \
                 W + (n0 + r) * KDIM + k0_ + c * 8);                                        \
        }                                                                                   \
        cp_commit();                                                                        \
    } while (0)

    LOAD_STAGE(0, 0);

    for (int kt = 0; kt < KDIM / 64; kt++) {
        const int buf = kt & 1;
        if (kt + 1 < KDIM / 64) { LOAD_STAGE(kt + 1, buf ^ 1); cp_wait1(); }
        else cp_wait0();
        __syncthreads();

        const uint32_t aw = sbA + (buf * 128 * GGP + wm * 64 * GGP) * 2;
        const uint32_t bw = sbB + (buf * 128 * GGP + wn * 32 * GGP) * 2;
        #pragma unroll
        for (int t = 0; t < 4; t++) {
            uint32_t Af[4][4];
            #pragma unroll
            for (int mi = 0; mi < 4; mi++)
                ldsm4(Af[mi], aw + (mi * 16 * GGP) * 2 + t * 32 + abase);
            uint32_t Bf[2][4];
            #pragma unroll
            for (int bi = 0; bi < 2; bi++)
                ldsm4(Bf[bi], bw + (bi * 16 * GGP) * 2 + t * 32 + kbase);
            #pragma unroll
            for (int mi = 0; mi < 4; mi++)
                #pragma unroll
                for (int bi = 0; bi < 2; bi++) {
                    mma16816(acc[mi][bi * 2],     Af[mi], Bf[bi]);
                    mma16816(acc[mi][bi * 2 + 1], Af[mi], Bf[bi] + 2);
                }
        }
        __syncthreads();
    }
    #undef LOAD_STAGE

    const int qr = lane >> 2, qc = (lane & 3) << 1;
    #pragma unroll
    for (int mi = 0; mi < 4; mi++) {
        int mrow = m0 + wm * 64 + mi * 16 + qr;
        #pragma unroll
        for (int g = 0; g < 4; g++) {
            int n = n0 + wn * 32 + g * 8 + qc;
            float b0 = bias[n], b1 = bias[n + 1];
            if (DENSE) {
                float2 u0 = { acc[mi][g][0] + b0, acc[mi][g][1] + b1 };
                float2 u1 = { acc[mi][g][2] + b0, acc[mi][g][3] + b1 };
                *reinterpret_cast<float2*>(outf + mrow * DMODEL + n)       = u0;
                *reinterpret_cast<float2*>(outf + (mrow + 8) * DMODEL + n) = u1;
            } else {
                uint32_t u0 = pack_h2((acc[mi][g][0] + b0) * scale, (acc[mi][g][1] + b1) * scale);
                uint32_t u1 = pack_h2((acc[mi][g][2] + b0) * scale, (acc[mi][g][3] + b1) * scale);
                *reinterpret_cast<uint32_t*>(outh + mrow * DMODEL + n)       = u0;
                *reinterpret_cast<uint32_t*>(outh + (mrow + 8) * DMODEL + n) = u1;
            }
        }
    }
}

// ---------------- fp16 mma.sync flash attention ----------------
// BM=128, 128 threads (4 warps x 32 q-rows), 2 CTAs/SM.
// Softmax on the fp16x2 path: cvt f32->f16x2, add (-inf) mask bias, ex2.f16x2
// (half the MUFU ops). Row sums accumulate on the TENSOR pipe via Ap @ ones.
#define QPITCH 144
#define OFF_Q   0
#define OFF_K0  (128 * QPITCH)
#define OFF_K1  (OFF_K0 + 64 * QPITCH)
#define OFF_V0  (OFF_K1 + 64 * QPITCH)
#define OFF_V1  (OFF_V0 + 64 * QPITCH)
#define FL_SMEM (OFF_V1 + 64 * QPITCH)         // (128+4*64)*144 = 55296 B

__global__ void __launch_bounds__(128, 2) flash_mma_kernel()
{
    extern __shared__ __align__(128) char smem[];
    const uint32_t sb = smem_u32(smem);
    const int tid  = threadIdx.x;
    const int wid  = tid >> 5;
    const int lane = tid & 31;
    const int h    = blockIdx.y;
    const int q0   = blockIdx.x * BM;
    const __half* Qg = g_Qh + h * (SEQ * HD);
    const __half* Kg = g_Kh + h * (SEQ * HD);
    const __half* Vg = g_Vh + h * (SEQ * HD);

    // ---- prologue: Q -> smem (padded); K0,V0 (group), K1 (group) ----
    {
        int r = tid;                              // 128 rows, one per thread
        const uint4* src = reinterpret_cast<const uint4*>(Qg + (q0 + r) * HD);
        char* dst = smem + OFF_Q + r * QPITCH;
        #pragma unroll
        for (int k = 0; k < 8; k++)
            reinterpret_cast<uint4*>(dst)[k] = src[k];
    }
    #pragma unroll
    for (int l = 0; l < 4; l++) {
        int idx = tid + l * 128;                  // 0..511
        int r = idx >> 3, ch = (idx & 7) << 3;
        cp16(sb + OFF_K0 + r * QPITCH + ch * 2, Kg + r * HD + ch);
        cp16(sb + OFF_V0 + r * QPITCH + ch * 2, Vg + r * HD + ch);
    }
    cp_commit();
    #pragma unroll
    for (int l = 0; l < 4; l++) {
        int idx = tid + l * 128;
        int r = idx >> 3, ch = (idx & 7) << 3;
        cp16(sb + OFF_K1 + r * QPITCH + ch * 2, Kg + BN * HD + r * HD + ch);
    }
    cp_commit();
    cp_wait0();
    __syncthreads();

    const int qb = wid * 32;
    const uint32_t abase = ((((lane >> 3) & 1) * 8 + (lane & 7)) * QPITCH) + (((lane >> 4) & 1) * 16);
    const uint32_t kbase = ((((lane >> 4) & 1) * 8 + (lane & 7)) * QPITCH) + (((lane >> 3) & 1) * 16);

    uint32_t Aq[2][4][4];
    #pragma unroll
    for (int u = 0; u < 2; u++)
        #pragma unroll
        for (int t = 0; t < 4; t++)
            ldsm4(Aq[u][t], sb + OFF_Q + (qb + u * 16) * QPITCH + t * 32 + abase);

    float Oacc[2][8][4];
    #pragma unroll
    for (int u = 0; u < 2; u++)
        #pragma unroll
        for (int j = 0; j < 8; j++)
            #pragma unroll
            for (int e = 0; e < 4; e++) Oacc[u][j][e] = 0.0f;

    float Lacc[2][4];   // row sums via ones-MMA (all n-columns equal)
    #pragma unroll
    for (int u = 0; u < 2; u++)
        #pragma unroll
        for (int e = 0; e < 4; e++) Lacc[u][e] = 0.0f;
    const uint32_t onesB[2] = { 0x3C003C00u, 0x3C003C00u };

    // ---- issue QK(0) from Kbuf0 (B-frag shared across both row-tiles) ----
    float S[2][8][4];
    #pragma unroll
    for (int u = 0; u < 2; u++)
        #pragma unroll
        for (int j = 0; j < 8; j++)
            #pragma unroll
            for (int e = 0; e < 4; e++) S[u][j][e] = 0.0f;
    #pragma unroll
    for (int jp = 0; jp < 4; jp++) {
        #pragma unroll
        for (int t = 0; t < 4; t++) {
            uint32_t B[4];
            ldsm4(B, sb + OFF_K0 + jp * (16 * QPITCH) + t * 32 + kbase);
            #pragma unroll
            for (int u = 0; u < 2; u++) {
                mma16816(S[u][2 * jp],     Aq[u][t], B);
                mma16816(S[u][2 * jp + 1], Aq[u][t], B + 2);
            }
        }
    }
    __syncthreads();   // LDSM(K0) done in all warps before iter-0 prefetch overwrites Kbuf0

    const int rowb = q0 + qb + (lane >> 2);
    const int qv = lane & 3;

    for (int i = 0; i < NKB; i++) {
        // --- prefetch K(i+2) -> kbuf[i&1], V(i+1) -> vbuf[(i+1)&1] ---
        if (i + 2 < NKB) {
            const uint32_t kn = sb + ((i & 1) ? OFF_K1 : OFF_K0);
            const __half* Kn = Kg + (i + 2) * BN * HD;
            #pragma unroll
            for (int l = 0; l < 4; l++) {
                int idx = tid + l * 128;
                int r = idx >> 3, ch = (idx & 7) << 3;
                cp16(kn + r * QPITCH + ch * 2, Kn + r * HD + ch);
            }
            cp_commit();
        }
        if (i + 1 < NKB) {
            const uint32_t vn = sb + (((i + 1) & 1) ? OFF_V1 : OFF_V0);
            const __half* Vn = Vg + (i + 1) * BN * HD;
            #pragma unroll
            for (int l = 0; l < 4; l++) {
                int idx = tid + l * 128;
                int r = idx >> 3, ch = (idx & 7) << 3;
                cp16(vn + r * QPITCH + ch * 2, Vn + r * HD + ch);
            }
            cp_commit();
        }

        // --- softmax(i): fp16x2 path. masked -> add(-inf) -> ex2 -> 0 exactly ---
        uint32_t Ap[2][4][4];
        #pragma unroll
        for (int u = 0; u < 2; u++) {
            uint2 m0 = *reinterpret_cast<const uint2*>(g_mb + (rowb + u * 16)     * NW + (i << 1));
            uint2 m1 = *reinterpret_cast<const uint2*>(g_mb + (rowb + u * 16 + 8) * NW + (i << 1));
            #pragma unroll
            for (int j = 0; j < 8; j++) {
                unsigned w0 = (j < 4) ? m0.x : m0.y;
                unsigned w1 = (j < 4) ? m1.x : m1.y;
                int p0 = ((j & 3) << 3) + (qv << 1);
                unsigned b01 = (w0 >> p0) & 3u;
                unsigned b23 = (w1 >> p0) & 3u;
                uint32_t bias01 = ((b01 & 1u) * 0xFC00u) | ((b01 >> 1) * 0xFC000000u);
                uint32_t bias23 = ((b23 & 1u) * 0xFC00u) | ((b23 >> 1) * 0xFC000000u);
                uint32_t h01 = pack_h2(S[u][j][0], S[u][j][1]);
                uint32_t h23 = pack_h2(S[u][j][2], S[u][j][3]);
                asm("add.rn.f16x2 %0, %1, %2;" : "=r"(h01) : "r"(h01), "r"(bias01));
                asm("add.rn.f16x2 %0, %1, %2;" : "=r"(h23) : "r"(h23), "r"(bias23));
                uint32_t p01, p23;
                asm("ex2.approx.f16x2 %0, %1;" : "=r"(p01) : "r"(h01));
                asm("ex2.approx.f16x2 %0, %1;" : "=r"(p23) : "r"(h23));
                int t = j >> 1;
                if ((j & 1) == 0) { Ap[u][t][0] = p01; Ap[u][t][1] = p23; }
                else              { Ap[u][t][2] = p01; Ap[u][t][3] = p23; }
            }
            // row sums on the tensor pipe: Lacc += Ap @ ones
            #pragma unroll
            for (int t = 0; t < 4; t++)
                mma16816(Lacc[u], Ap[u][t], onesB);
        }

        // --- fused MMA issue: QK(i+1) + PV(i), B-frags reused across row-tiles ---
        const uint32_t vcur = sb + ((i & 1) ? OFF_V1 : OFF_V0);
        if (i + 1 < NKB) {
            const uint32_t kcur = sb + (((i + 1) & 1) ? OFF_K1 : OFF_K0);
            #pragma unroll
            for (int u = 0; u < 2; u++)
                #pragma unroll
                for (int j = 0; j < 8; j++)
                    #pragma unroll
                    for (int e = 0; e < 4; e++) S[u][j][e] = 0.0f;
            #pragma unroll
            for (int jp = 0; jp < 4; jp++) {
                #pragma unroll
                for (int t = 0; t < 4; t++) {
                    uint32_t Bk[4];
                    ldsm4(Bk, kcur + jp * (16 * QPITCH) + t * 32 + kbase);
                    uint32_t Bv[4];
                    ldsm4t(Bv, vcur + t * (16 * QPITCH) + jp * 32 + abase);
                    #pragma unroll
                    for (int u = 0; u < 2; u++) {
                        mma16816(S[u][2 * jp],        Aq[u][t], Bk);
                        mma16816(S[u][2 * jp + 1],    Aq[u][t], Bk + 2);
                        mma16816(Oacc[u][2 * jp],     Ap[u][t], Bv);
                        mma16816(Oacc[u][2 * jp + 1], Ap[u][t], Bv + 2);
                    }
                }
            }
        } else {
            #pragma unroll
            for (int jp = 0; jp < 4; jp++) {
                #pragma unroll
                for (int t = 0; t < 4; t++) {
                    uint32_t Bv[4];
                    ldsm4t(Bv, vcur + t * (16 * QPITCH) + jp * 32 + abase);
                    #pragma unroll
                    for (int u = 0; u < 2; u++) {
                        mma16816(Oacc[u][2 * jp],     Ap[u][t], Bv);
                        mma16816(Oacc[u][2 * jp + 1], Ap[u][t], Bv + 2);
                    }
                }
            }
        }

        cp_wait0();
        __syncthreads();
    }

    // ---- epilogue: Lacc already holds exact fp32 row sums (no shuffles) ----
    #pragma unroll
    for (int u = 0; u < 2; u++) {
        float inv0 = 1.0f / Lacc[u][0];
        float inv1 = 1.0f / Lacc[u][2];

        __half* C0 = g_Ch + h * (SEQ * HD) + (rowb + u * 16) * HD;
        __half* C1 = C0 + 8 * HD;
        #pragma unroll
        for (int j = 0; j < 8; j++) {
            int c = 8 * j + (qv << 1);
            *reinterpret_cast<uint32_t*>(C0 + c) = pack_h2(Oacc[u][j][0] * inv0, Oacc[u][j][1] * inv0);
            *reinterpret_cast<uint32_t*>(C1 + c) = pack_h2(Oacc[u][j][2] * inv1, Oacc[u][j][3] * inv1);
        }
    }
}

// ---------------- launch ----------------
extern "C" void kernel_launch(void* const* d_in, const int* in_sizes, int n_in,
                              void* d_out, int out_size)
{
    (void)in_sizes; (void)n_in; (void)out_size;
    const float* x  = (const float*)d_in[0];
    const int*   mk = (const int*)d_in[1];
    const float* wq = (const float*)d_in[2];
    const float* bq = (const float*)d_in[3];
    const float* wk = (const float*)d_in[4];
    const float* bk = (const float*)d_in[5];
    const float* wv = (const float*)d_in[6];
    const float* bv = (const float*)d_in[7];
    const float* dw = (const float*)d_in[8];
    const float* db = (const float*)d_in[9];
    float* out = (float*)d_out;

    cudaFuncSetAttribute(flash_mma_kernel,
                         cudaFuncAttributeMaxDynamicSharedMemorySize, FL_SMEM);

    convert_mask_kernel<<<3072 + 16384, 256>>>(x, wq, wk, wv, dw, mk);
    hmma_gemm_kernel<false><<<dim3(DMODEL / 128, SEQ / 128, 3), 256>>>(nullptr, nullptr, bq, bk, bv);
    flash_mma_kernel<<<dim3(SEQ / BM, NH), 128, FL_SMEM>>>();
    hmma_gemm_kernel<true><<<dim3(DMODEL / 128, SEQ / 128), 256>>>(out, db, nullptr, nullptr, nullptr);
}

// round 16
// speedup vs baseline: 1.4258x; 1.0113x over previous
#include <cuda_runtime.h>
#include <cuda_fp16.h>
#include <cstdint>

#define SEQ    4096
#define DMODEL 512
#define NH     8
#define HD     64
#define KDIM   512
#define NW     (SEQ / 32)   // 128 mask words per row

#define BM 128
#define BN 64
#define NKB (SEQ / BN)

// 0.125 * log2(e): folded into Q projection so flash does exp2(S) directly
#define QSCALE 0.18033688011112042f

// ---------------- scratch (device globals; no allocation allowed) ----------------
__device__ __half   g_Xh[SEQ * KDIM];          // fp16 copy of x
__device__ __half   g_Wh[4 * DMODEL * KDIM];   // wq, wk, wv, dense (fp16)
__device__ __half   g_Qh[SEQ * DMODEL];        // pre-scaled by QSCALE
__device__ __half   g_Kh[SEQ * DMODEL];
__device__ __half   g_Vh[SEQ * DMODEL];
__device__ __half   g_Ch[SEQ * DMODEL];        // context (head-major), fp16
__device__ unsigned g_mb[SEQ * NW];

// ================= helpers =================
__device__ __forceinline__ uint32_t smem_u32(const void* p) {
    uint32_t a;
    asm("{ .reg .u64 t; cvta.to.shared.u64 t, %1; cvt.u32.u64 %0, t; }" : "=r"(a) : "l"(p));
    return a;
}
__device__ __forceinline__ void cp16(uint32_t dst, const void* src) {
    asm volatile("cp.async.cg.shared.global [%0], [%1], 16;" :: "r"(dst), "l"(src));
}
__device__ __forceinline__ void cp_commit() { asm volatile("cp.async.commit_group;"); }
__device__ __forceinline__ void cp_wait0()  { asm volatile("cp.async.wait_group 0;" ::: "memory"); }
__device__ __forceinline__ void cp_wait1()  { asm volatile("cp.async.wait_group 1;" ::: "memory"); }

__device__ __forceinline__ void ldsm4(uint32_t* r, uint32_t addr) {
    asm volatile("ldmatrix.sync.aligned.m8n8.x4.shared.b16 {%0,%1,%2,%3}, [%4];"
        : "=r"(r[0]), "=r"(r[1]), "=r"(r[2]), "=r"(r[3]) : "r"(addr));
}
__device__ __forceinline__ void ldsm4t(uint32_t* r, uint32_t addr) {
    asm volatile("ldmatrix.sync.aligned.m8n8.x4.trans.shared.b16 {%0,%1,%2,%3}, [%4];"
        : "=r"(r[0]), "=r"(r[1]), "=r"(r[2]), "=r"(r[3]) : "r"(addr));
}
// D = A*B + D   (m16n8k16, f16 in, f32 accum)
__device__ __forceinline__ void mma16816(float* d, const uint32_t* a, const uint32_t* b) {
    asm volatile("mma.sync.aligned.m16n8k16.row.col.f32.f16.f16.f32 "
        "{%0,%1,%2,%3}, {%4,%5,%6,%7}, {%8,%9}, {%0,%1,%2,%3};"
        : "+f"(d[0]), "+f"(d[1]), "+f"(d[2]), "+f"(d[3])
        : "r"(a[0]), "r"(a[1]), "r"(a[2]), "r"(a[3]), "r"(b[0]), "r"(b[1]));
}
// D = A*B + Z   (separate C operand; Z stays zero -> no S re-zeroing movs)
__device__ __forceinline__ void mma16816_zc(float* d, const uint32_t* a, const uint32_t* b,
                                            const float* z) {
    asm volatile("mma.sync.aligned.m16n8k16.row.col.f32.f16.f16.f32 "
        "{%0,%1,%2,%3}, {%4,%5,%6,%7}, {%8,%9}, {%10,%11,%12,%13};"
        : "=f"(d[0]), "=f"(d[1]), "=f"(d[2]), "=f"(d[3])
        : "r"(a[0]), "r"(a[1]), "r"(a[2]), "r"(a[3]), "r"(b[0]), "r"(b[1]),
          "f"(z[0]), "f"(z[1]), "f"(z[2]), "f"(z[3]));
}
__device__ __forceinline__ uint32_t pack_h2(float a, float b) {
    __half2 h = __floats2half2_rn(a, b);
    return *reinterpret_cast<uint32_t*>(&h);
}

// ---------------- convert (x + weights -> fp16) + mask pack, one launch ----------------
__global__ __launch_bounds__(256) void convert_mask_kernel(
    const float* __restrict__ x,  const float* __restrict__ wq,
    const float* __restrict__ wk, const float* __restrict__ wv,
    const float* __restrict__ dw, const int* __restrict__ mk)
{
    const int tid = threadIdx.x;
    if (blockIdx.x < 3072) {
        int f4 = blockIdx.x * 256 + tid;   // 0 .. 786431
        const float4* src; __half* dst; int off;
        if (f4 < 524288) { src = (const float4*)x; off = f4; dst = g_Xh; }
        else {
            int t = f4 - 524288;
            int w = t >> 16; off = t & 65535;
            src = (const float4*)(w == 0 ? wq : w == 1 ? wk : w == 2 ? wv : dw);
            dst = g_Wh + w * (DMODEL * KDIM);
        }
        float4 v = src[off];
        uint2 u = { pack_h2(v.x, v.y), pack_h2(v.z, v.w) };
        *reinterpret_cast<uint2*>(dst + off * 4) = u;
    } else {
        const int base = (blockIdx.x - 3072) * 1024;     // int index, 1024 ints/CTA
        uint4 v = *reinterpret_cast<const uint4*>(mk + base + tid * 4);
        unsigned n = (v.x != 0 ? 1u : 0u) | (v.y != 0 ? 2u : 0u)
                   | (v.z != 0 ? 4u : 0u) | (v.w != 0 ? 8u : 0u);
        n |= __shfl_xor_sync(0xffffffffu, n, 1) << 4;
        n |= __shfl_xor_sync(0xffffffffu, n, 2) << 8;
        n |= __shfl_xor_sync(0xffffffffu, n, 4) << 16;
        if ((tid & 7) == 0)
            g_mb[(base >> 5) + (tid >> 3)] = n;
    }
}

// ---------------- HMMA GEMM: out = (A @ W^T + bias) * scale ----------------
// TMxN=TMx128 tile, BK=64, 256 threads (8 warps as 2x4), cp.async double buffer.
// TM=128 for QKV (384 CTAs); TM=64 for dense (256 CTAs -> latency-bound fix).
#define GGP 72

template<int TM, bool DENSE>
__global__ __launch_bounds__(256) void hmma_gemm_kernel(
    float* __restrict__ outf, const float* __restrict__ dense_b,
    const float* __restrict__ bq, const float* __restrict__ bk,
    const float* __restrict__ bv)
{
    constexpr int MI = TM / 32;    // m-frags per m-warp (wm covers TM/2 rows)
    __shared__ __half sA[2][TM * GGP];
    __shared__ __half sB[2][128 * GGP];

    const int tid = threadIdx.x, lane = tid & 31, wid = tid >> 5;
    const int wm = wid & 1, wn = wid >> 1;
    const int m0 = blockIdx.y * TM, n0 = blockIdx.x * 128;
    const int z = DENSE ? 3 : blockIdx.z;

    const __half* W = g_Wh + z * (DMODEL * KDIM);
    const float* bias = DENSE ? dense_b : (z == 0 ? bq : z == 1 ? bk : bv);
    __half* outh = DENSE ? nullptr : (z == 0 ? g_Qh : z == 1 ? g_Kh : g_Vh);
    const float scale = (!DENSE && z == 0) ? QSCALE : 1.0f;

    const uint32_t sbA = smem_u32(sA), sbB = smem_u32(sB);

    float acc[MI][4][4];
    #pragma unroll
    for (int mi = 0; mi < MI; mi++)
        #pragma unroll
        for (int g = 0; g < 4; g++)
            #pragma unroll
            for (int e = 0; e < 4; e++) acc[mi][g][e] = 0.0f;

    const uint32_t abase = ((((lane >> 3) & 1) * 8 + (lane & 7)) * GGP) * 2 + ((lane >> 4) & 1) * 16;
    const uint32_t kbase = ((((lane >> 4) & 1) * 8 + (lane & 7)) * GGP) * 2 + ((lane >> 3) & 1) * 16;

    #define LOAD_STAGE(kt, buf) do {                                                        \
        const int k0_ = (kt) * 64;                                                          \
        _Pragma("unroll")                                                                   \
        for (int l = 0; l < TM / 32; l++) {                                                 \
            int idx = tid + l * 256;                                                        \
            int r = idx >> 3, c = idx & 7;                                                  \
            const __half* asrc = DENSE                                                      \
                ? (g_Ch + (k0_ >> 6) * (SEQ * HD) + (m0 + r) * HD + c * 8)                  \
                : (g_Xh + (m0 + r) * KDIM + k0_ + c * 8);                                   \
            cp16(sbA + ((buf) * TM * GGP + r * GGP) * 2 + c * 16, asrc);                    \
        }                                                                                   \
        _Pragma("unroll")                                                                   \
        for (int l = 0; l < 4; l++) {                                                       \
            int idx = tid + l * 256;                                                        \
            int r = idx >> 3, c = idx & 7;                                                  \
            cp16(sbB + ((buf) * 128 * GGP + r * GGP) * 2 + c * 16,                          \
                 W + (n0 + r) * KDIM + k0_ + c * 8);                                        \
        }                                                                                   \
        cp_commit();                                                                        \
    } while (0)

    LOAD_STAGE(0, 0);

    for (int kt = 0; kt < KDIM / 64; kt++) {
        const int buf = kt & 1;
        if (kt + 1 < KDIM / 64) { LOAD_STAGE(kt + 1, buf ^ 1); cp_wait1(); }
        else cp_wait0();
        __syncthreads();

        const uint32_t aw = sbA + (buf * TM * GGP + wm * (TM / 2) * GGP) * 2;
        const uint32_t bw = sbB + (buf * 128 * GGP + wn * 32 * GGP) * 2;
        #pragma unroll
        for (int t = 0; t < 4; t++) {
            uint32_t Af[MI][4];
            #pragma unroll
            for (int mi = 0; mi < MI; mi++)
                ldsm4(Af[mi], aw + (mi * 16 * GGP) * 2 + t * 32 + abase);
            uint32_t Bf[2][4];
            #pragma unroll
            for (int bi = 0; bi < 2; bi++)
                ldsm4(Bf[bi], bw + (bi * 16 * GGP) * 2 + t * 32 + kbase);
            #pragma unroll
            for (int mi = 0; mi < MI; mi++)
                #pragma unroll
                for (int bi = 0; bi < 2; bi++) {
                    mma16816(acc[mi][bi * 2],     Af[mi], Bf[bi]);
                    mma16816(acc[mi][bi * 2 + 1], Af[mi], Bf[bi] + 2);
                }
        }
        __syncthreads();
    }
    #undef LOAD_STAGE

    const int qr = lane >> 2, qc = (lane & 3) << 1;
    #pragma unroll
    for (int mi = 0; mi < MI; mi++) {
        int mrow = m0 + wm * (TM / 2) + mi * 16 + qr;
        #pragma unroll
        for (int g = 0; g < 4; g++) {
            int n = n0 + wn * 32 + g * 8 + qc;
            float b0 = bias[n], b1 = bias[n + 1];
            if (DENSE) {
                float2 u0 = { acc[mi][g][0] + b0, acc[mi][g][1] + b1 };
                float2 u1 = { acc[mi][g][2] + b0, acc[mi][g][3] + b1 };
                *reinterpret_cast<float2*>(outf + mrow * DMODEL + n)       = u0;
                *reinterpret_cast<float2*>(outf + (mrow + 8) * DMODEL + n) = u1;
            } else {
                uint32_t u0 = pack_h2((acc[mi][g][0] + b0) * scale, (acc[mi][g][1] + b1) * scale);
                uint32_t u1 = pack_h2((acc[mi][g][2] + b0) * scale, (acc[mi][g][3] + b1) * scale);
                *reinterpret_cast<uint32_t*>(outh + mrow * DMODEL + n)       = u0;
                *reinterpret_cast<uint32_t*>(outh + (mrow + 8) * DMODEL + n) = u1;
            }
        }
    }
}

// ---------------- fp16 mma.sync flash attention ----------------
// BM=128, 128 threads (4 warps x 32 q-rows), 2 CTAs/SM.
// Softmax on fp16x2 (ex2.f16x2 + (-inf) mask bias); row sums via ones-MMA.
// S fragments written by zero-C MMA on the first K-step (no re-zero movs).
#define QPITCH 144
#define OFF_Q   0
#define OFF_K0  (128 * QPITCH)
#define OFF_K1  (OFF_K0 + 64 * QPITCH)
#define OFF_V0  (OFF_K1 + 64 * QPITCH)
#define OFF_V1  (OFF_V0 + 64 * QPITCH)
#define FL_SMEM (OFF_V1 + 64 * QPITCH)         // (128+4*64)*144 = 55296 B

__global__ void __launch_bounds__(128, 2) flash_mma_kernel()
{
    extern __shared__ __align__(128) char smem[];
    const uint32_t sb = smem_u32(smem);
    const int tid  = threadIdx.x;
    const int wid  = tid >> 5;
    const int lane = tid & 31;
    const int h    = blockIdx.y;
    const int q0   = blockIdx.x * BM;
    const __half* Qg = g_Qh + h * (SEQ * HD);
    const __half* Kg = g_Kh + h * (SEQ * HD);
    const __half* Vg = g_Vh + h * (SEQ * HD);

    // ---- prologue: Q -> smem (padded); K0,V0 (group), K1 (group) ----
    {
        int r = tid;                              // 128 rows, one per thread
        const uint4* src = reinterpret_cast<const uint4*>(Qg + (q0 + r) * HD);
        char* dst = smem + OFF_Q + r * QPITCH;
        #pragma unroll
        for (int k = 0; k < 8; k++)
            reinterpret_cast<uint4*>(dst)[k] = src[k];
    }
    #pragma unroll
    for (int l = 0; l < 4; l++) {
        int idx = tid + l * 128;                  // 0..511
        int r = idx >> 3, ch = (idx & 7) << 3;
        cp16(sb + OFF_K0 + r * QPITCH + ch * 2, Kg + r * HD + ch);
        cp16(sb + OFF_V0 + r * QPITCH + ch * 2, Vg + r * HD + ch);
    }
    cp_commit();
    #pragma unroll
    for (int l = 0; l < 4; l++) {
        int idx = tid + l * 128;
        int r = idx >> 3, ch = (idx & 7) << 3;
        cp16(sb + OFF_K1 + r * QPITCH + ch * 2, Kg + BN * HD + r * HD + ch);
    }
    cp_commit();
    cp_wait0();
    __syncthreads();

    const int qb = wid * 32;
    const uint32_t abase = ((((lane >> 3) & 1) * 8 + (lane & 7)) * QPITCH) + (((lane >> 4) & 1) * 16);
    const uint32_t kbase = ((((lane >> 4) & 1) * 8 + (lane & 7)) * QPITCH) + (((lane >> 3) & 1) * 16);

    uint32_t Aq[2][4][4];
    #pragma unroll
    for (int u = 0; u < 2; u++)
        #pragma unroll
        for (int t = 0; t < 4; t++)
            ldsm4(Aq[u][t], sb + OFF_Q + (qb + u * 16) * QPITCH + t * 32 + abase);

    float Oacc[2][8][4];
    #pragma unroll
    for (int u = 0; u < 2; u++)
        #pragma unroll
        for (int j = 0; j < 8; j++)
            #pragma unroll
            for (int e = 0; e < 4; e++) Oacc[u][j][e] = 0.0f;

    float Lacc[2][4];   // row sums via ones-MMA
    #pragma unroll
    for (int u = 0; u < 2; u++)
        #pragma unroll
        for (int e = 0; e < 4; e++) Lacc[u][e] = 0.0f;
    const uint32_t onesB[2] = { 0x3C003C00u, 0x3C003C00u };
    const float Zf[4] = { 0.0f, 0.0f, 0.0f, 0.0f };   // zero-C operand (folds to RZ)

    // ---- issue QK(0) from Kbuf0 ----
    float S[2][8][4];
    #pragma unroll
    for (int jp = 0; jp < 4; jp++) {
        #pragma unroll
        for (int t = 0; t < 4; t++) {
            uint32_t B[4];
            ldsm4(B, sb + OFF_K0 + jp * (16 * QPITCH) + t * 32 + kbase);
            #pragma unroll
            for (int u = 0; u < 2; u++) {
                if (t == 0) {
                    mma16816_zc(S[u][2 * jp],     Aq[u][t], B,     Zf);
                    mma16816_zc(S[u][2 * jp + 1], Aq[u][t], B + 2, Zf);
                } else {
                    mma16816(S[u][2 * jp],     Aq[u][t], B);
                    mma16816(S[u][2 * jp + 1], Aq[u][t], B + 2);
                }
            }
        }
    }
    __syncthreads();   // LDSM(K0) done in all warps before iter-0 prefetch overwrites Kbuf0

    const int rowb = q0 + qb + (lane >> 2);
    const int qv = lane & 3;

    for (int i = 0; i < NKB; i++) {
        // --- prefetch K(i+2) -> kbuf[i&1], V(i+1) -> vbuf[(i+1)&1] ---
        if (i + 2 < NKB) {
            const uint32_t kn = sb + ((i & 1) ? OFF_K1 : OFF_K0);
            const __half* Kn = Kg + (i + 2) * BN * HD;
            #pragma unroll
            for (int l = 0; l < 4; l++) {
                int idx = tid + l * 128;
                int r = idx >> 3, ch = (idx & 7) << 3;
                cp16(kn + r * QPITCH + ch * 2, Kn + r * HD + ch);
            }
            cp_commit();
        }
        if (i + 1 < NKB) {
            const uint32_t vn = sb + (((i + 1) & 1) ? OFF_V1 : OFF_V0);
            const __half* Vn = Vg + (i + 1) * BN * HD;
            #pragma unroll
            for (int l = 0; l < 4; l++) {
                int idx = tid + l * 128;
                int r = idx >> 3, ch = (idx & 7) << 3;
                cp16(vn + r * QPITCH + ch * 2, Vn + r * HD + ch);
            }
            cp_commit();
        }

        // --- softmax(i): fp16x2 path. masked -> add(-inf) -> ex2 -> 0 exactly ---
        uint32_t Ap[2][4][4];
        #pragma unroll
        for (int u = 0; u < 2; u++) {
            uint2 m0 = *reinterpret_cast<const uint2*>(g_mb + (rowb + u * 16)     * NW + (i << 1));
            uint2 m1 = *reinterpret_cast<const uint2*>(g_mb + (rowb + u * 16 + 8) * NW + (i << 1));
            #pragma unroll
            for (int j = 0; j < 8; j++) {
                unsigned w0 = (j < 4) ? m0.x : m0.y;
                unsigned w1 = (j < 4) ? m1.x : m1.y;
                int p0 = ((j & 3) << 3) + (qv << 1);
                unsigned b01 = (w0 >> p0) & 3u;
                unsigned b23 = (w1 >> p0) & 3u;
                uint32_t bias01 = ((b01 & 1u) * 0xFC00u) | ((b01 >> 1) * 0xFC000000u);
                uint32_t bias23 = ((b23 & 1u) * 0xFC00u) | ((b23 >> 1) * 0xFC000000u);
                uint32_t h01 = pack_h2(S[u][j][0], S[u][j][1]);
                uint32_t h23 = pack_h2(S[u][j][2], S[u][j][3]);
                asm("add.rn.f16x2 %0, %1, %2;" : "=r"(h01) : "r"(h01), "r"(bias01));
                asm("add.rn.f16x2 %0, %1, %2;" : "=r"(h23) : "r"(h23), "r"(bias23));
                uint32_t p01, p23;
                asm("ex2.approx.f16x2 %0, %1;" : "=r"(p01) : "r"(h01));
                asm("ex2.approx.f16x2 %0, %1;" : "=r"(p23) : "r"(h23));
                int t = j >> 1;
                if ((j & 1) == 0) { Ap[u][t][0] = p01; Ap[u][t][1] = p23; }
                else              { Ap[u][t][2] = p01; Ap[u][t][3] = p23; }
            }
            #pragma unroll
            for (int t = 0; t < 4; t++)
                mma16816(Lacc[u], Ap[u][t], onesB);
        }

        // --- fused MMA issue: QK(i+1) (zero-C first step) + PV(i) ---
        const uint32_t vcur = sb + ((i & 1) ? OFF_V1 : OFF_V0);
        if (i + 1 < NKB) {
            const uint32_t kcur = sb + (((i + 1) & 1) ? OFF_K1 : OFF_K0);
            #pragma unroll
            for (int jp = 0; jp < 4; jp++) {
                #pragma unroll
                for (int t = 0; t < 4; t++) {
                    uint32_t Bk[4];
                    ldsm4(Bk, kcur + jp * (16 * QPITCH) + t * 32 + kbase);
                    uint32_t Bv[4];
                    ldsm4t(Bv, vcur + t * (16 * QPITCH) + jp * 32 + abase);
                    #pragma unroll
                    for (int u = 0; u < 2; u++) {
                        if (t == 0) {
                            mma16816_zc(S[u][2 * jp],     Aq[u][t], Bk,     Zf);
                            mma16816_zc(S[u][2 * jp + 1], Aq[u][t], Bk + 2, Zf);
                        } else {
                            mma16816(S[u][2 * jp],     Aq[u][t], Bk);
                            mma16816(S[u][2 * jp + 1], Aq[u][t], Bk + 2);
                        }
                        mma16816(Oacc[u][2 * jp],     Ap[u][t], Bv);
                        mma16816(Oacc[u][2 * jp + 1], Ap[u][t], Bv + 2);
                    }
                }
            }
        } else {
            #pragma unroll
            for (int jp = 0; jp < 4; jp++) {
                #pragma unroll
                for (int t = 0; t < 4; t++) {
                    uint32_t Bv[4];
                    ldsm4t(Bv, vcur + t * (16 * QPITCH) + jp * 32 + abase);
                    #pragma unroll
                    for (int u = 0; u < 2; u++) {
                        mma16816(Oacc[u][2 * jp],     Ap[u][t], Bv);
                        mma16816(Oacc[u][2 * jp + 1], Ap[u][t], Bv + 2);
                    }
                }
            }
        }

        cp_wait0();
        __syncthreads();
    }

    // ---- epilogue: Lacc holds exact fp32 row sums ----
    #pragma unroll
    for (int u = 0; u < 2; u++) {
        float inv0 = 1.0f / Lacc[u][0];
        float inv1 = 1.0f / Lacc[u][2];

        __half* C0 = g_Ch + h * (SEQ * HD) + (rowb + u * 16) * HD;
        __half* C1 = C0 + 8 * HD;
        #pragma unroll
        for (int j = 0; j < 8; j++) {
            int c = 8 * j + (qv << 1);
            *reinterpret_cast<uint32_t*>(C0 + c) = pack_h2(Oacc[u][j][0] * inv0, Oacc[u][j][1] * inv0);
            *reinterpret_cast<uint32_t*>(C1 + c) = pack_h2(Oacc[u][j][2] * inv1, Oacc[u][j][3] * inv1);
        }
    }
}

// ---------------- launch ----------------
extern "C" void kernel_launch(void* const* d_in, const int* in_sizes, int n_in,
                              void* d_out, int out_size)
{
    (void)in_sizes; (void)n_in; (void)out_size;
    const float* x  = (const float*)d_in[0];
    const int*   mk = (const int*)d_in[1];
    const float* wq = (const float*)d_in[2];
    const float* bq = (const float*)d_in[3];
    const float* wk = (const float*)d_in[4];
    const float* bk = (const float*)d_in[5];
    const float* wv = (const float*)d_in[6];
    const float* bv = (const float*)d_in[7];
    const float* dw = (const float*)d_in[8];
    const float* db = (const float*)d_in[9];
    float* out = (float*)d_out;

    cudaFuncSetAttribute(flash_mma_kernel,
                         cudaFuncAttributeMaxDynamicSharedMemorySize, FL_SMEM);

    convert_mask_kernel<<<3072 + 16384, 256>>>(x, wq, wk, wv, dw, mk);
    hmma_gemm_kernel<128, false><<<dim3(DMODEL / 128, SEQ / 128, 3), 256>>>(nullptr, nullptr, bq, bk, bv);
    flash_mma_kernel<<<dim3(SEQ / BM, NH), 128, FL_SMEM>>>();
    hmma_gemm_kernel<64, true><<<dim3(DMODEL / 128, SEQ / 64), 256>>>(out, db, nullptr, nullptr, nullptr);
}